// round 2
// baseline (speedup 1.0000x reference)
#include <cuda_runtime.h>
#include <math.h>

// ---------------------------------------------------------------------------
// ProtICU: 3x(conv1d k=5 + relu + maxpool2) -> 2x 1x1 conv -> prototype L2
// distances -> min over patches -> log-sim -> sigmoid head.
// All intermediates kept in (B, L, C) layout (C contiguous) so every conv
// stage has coalesced loads and the thread=output-channel mapping gives
// coalesced stores.
// ---------------------------------------------------------------------------

#define NB 32

// Scratch (device globals: no allocation allowed in kernel_launch)
__device__ float g_h1[NB * 1024 * 128];
__device__ float g_h2[NB * 512 * 128];
__device__ float g_h3[NB * 256 * 128];
__device__ float g_f [NB * 256 * 128];
__device__ float g_fsq[NB * 256];
__device__ float g_w1t[76 * 5 * 128];
__device__ float g_w2t[128 * 5 * 128];
__device__ float g_w3t[128 * 5 * 128];
__device__ float g_wo1t[128 * 128];
__device__ float g_wo2t[128 * 128];
__device__ float g_pt[128 * 128];     // pt[d*128+p] = proto[p][d]
__device__ float g_psq[128];
__device__ float g_minpart[NB * 4 * 128];

// ---------------------------------------------------------------------------
// Prep: transpose all weights so the hot loops load coalesced.
//  w*t[(c*5+k)*128 + o] = W[o][c][k];  wo*t[c*128+o] = Wo[o][c];
//  pt[d*128+p] = proto[p][d];  psq[p] = ||proto[p]||^2
// ---------------------------------------------------------------------------
__global__ void prep_kernel(const float* __restrict__ W1, const float* __restrict__ W2,
                            const float* __restrict__ W3, const float* __restrict__ Wo1,
                            const float* __restrict__ Wo2, const float* __restrict__ proto) {
    const int stride = gridDim.x * blockDim.x;
    for (int i = blockIdx.x * blockDim.x + threadIdx.x; i < 128 * 5 * 128; i += stride) {
        const int o  = i & 127;
        const int ck = i >> 7;
        const int c = ck / 5, k = ck - 5 * c;
        if (i < 76 * 5 * 128) g_w1t[i] = W1[(o * 76 + c) * 5 + k];
        g_w2t[i] = W2[(o * 128 + c) * 5 + k];
        g_w3t[i] = W3[(o * 128 + c) * 5 + k];
        if (i < 128 * 128) {
            g_wo1t[i] = Wo1[o * 128 + ck];
            g_wo2t[i] = Wo2[o * 128 + ck];
            g_pt[i]   = proto[o * 128 + ck];  // i = d*128+p: o=p, ck=d
        }
        if (i < 128) {
            float s = 0.f;
            for (int d = 0; d < 128; d++) { float v = proto[i * 128 + d]; s = fmaf(v, v, s); }
            g_psq[i] = s;
        }
    }
}

// ---------------------------------------------------------------------------
// Fused conv1d(k=5, same) + ReLU + maxpool2.
// Block: 128 threads = output channels. Tile: 32 pre-pool positions
// (16 pooled). x tile staged in SMEM, weights staged in 4-channel chunks,
// x row hoisted to registers -> LDS:FFMA ~= 41:160 (FFMA-pipe bound).
// ---------------------------------------------------------------------------
template <int CIN>
__global__ void __launch_bounds__(128)
conv_pool_kernel(const float* __restrict__ in, const float* __restrict__ wt,
                 const float* __restrict__ bias, float* __restrict__ out,
                 int Lin, int Lpool) {
    constexpr int TPRE = 32;
    constexpr int XS   = TPRE + 4;
    __shared__ float xs[XS * CIN];
    __shared__ float ws[4 * 5 * 128];

    const int b      = blockIdx.y;
    const int l_pre0 = blockIdx.x * TPRE;
    const int o      = threadIdx.x;

    const float* inb = in + (size_t)b * Lin * CIN;
    for (int i = o; i < XS * CIN; i += 128) {
        const int pos = i / CIN;
        const int c   = i - pos * CIN;
        const int l   = l_pre0 - 2 + pos;
        xs[i] = (l >= 0 && l < Lin) ? inb[(size_t)l * CIN + c] : 0.f;
    }

    float acc[TPRE];
    const float bv = bias[o];
#pragma unroll
    for (int j = 0; j < TPRE; j++) acc[j] = bv;

    for (int c0 = 0; c0 < CIN; c0 += 4) {
        __syncthreads();  // xs ready (first iter) / ws no longer read (later iters)
        const float* wsrc = wt + c0 * 5 * 128;
        for (int i = o; i < 4 * 5 * 128; i += 128) ws[i] = wsrc[i];
        __syncthreads();
#pragma unroll
        for (int cc = 0; cc < 4; cc++) {
            float xr[XS];
#pragma unroll
            for (int p = 0; p < XS; p++) xr[p] = xs[p * CIN + c0 + cc];  // broadcast LDS
#pragma unroll
            for (int k = 0; k < 5; k++) {
                const float wv = ws[(cc * 5 + k) * 128 + o];
#pragma unroll
                for (int j = 0; j < TPRE; j++) acc[j] = fmaf(wv, xr[j + k], acc[j]);
            }
        }
    }

    float* outb = out + ((size_t)b * Lpool + blockIdx.x * 16) * 128;
#pragma unroll
    for (int j = 0; j < 16; j++) {
        const float v = fmaxf(fmaxf(acc[2 * j], acc[2 * j + 1]), 0.f);
        outb[(size_t)j * 128 + o] = v;  // coalesced over o
    }
}

// ---------------------------------------------------------------------------
// Two fused 1x1 convs (channel matmuls) with ReLU.
// Block: 128 threads = out channel, tile of 16 L-rows.
// ---------------------------------------------------------------------------
__global__ void __launch_bounds__(128)
fc_kernel(const float* __restrict__ in, const float* __restrict__ w1t,
          const float* __restrict__ b1, const float* __restrict__ w2t,
          const float* __restrict__ b2, float* __restrict__ f) {
    __shared__ float hs[16 * 128];
    __shared__ float ws[16 * 128];
    __shared__ float ms[16 * 128];

    const int b    = blockIdx.y;
    const int row0 = blockIdx.x * 16;
    const int o    = threadIdx.x;

    const float* inb = in + ((size_t)b * 256 + row0) * 128;
    for (int i = o; i < 2048; i += 128) hs[i] = inb[i];

    float acc[16];
    float bv = b1[o];
#pragma unroll
    for (int j = 0; j < 16; j++) acc[j] = bv;

    for (int c0 = 0; c0 < 128; c0 += 16) {
        __syncthreads();
        for (int i = o; i < 2048; i += 128) ws[i] = w1t[c0 * 128 + i];
        __syncthreads();
#pragma unroll
        for (int cc = 0; cc < 16; cc++) {
            const float wv = ws[cc * 128 + o];
#pragma unroll
            for (int j = 0; j < 16; j++) acc[j] = fmaf(wv, hs[j * 128 + c0 + cc], acc[j]);
        }
    }
    __syncthreads();
#pragma unroll
    for (int j = 0; j < 16; j++) ms[j * 128 + o] = fmaxf(acc[j], 0.f);

    bv = b2[o];
#pragma unroll
    for (int j = 0; j < 16; j++) acc[j] = bv;

    for (int c0 = 0; c0 < 128; c0 += 16) {
        __syncthreads();
        for (int i = o; i < 2048; i += 128) ws[i] = w2t[c0 * 128 + i];
        __syncthreads();
#pragma unroll
        for (int cc = 0; cc < 16; cc++) {
            const float wv = ws[cc * 128 + o];
#pragma unroll
            for (int j = 0; j < 16; j++) acc[j] = fmaf(wv, ms[j * 128 + c0 + cc], acc[j]);
        }
    }

    float* fb = f + ((size_t)b * 256 + row0) * 128;
#pragma unroll
    for (int j = 0; j < 16; j++) fb[j * 128 + o] = fmaxf(acc[j], 0.f);
}

// ---------------------------------------------------------------------------
// fsq[row] = ||f_row||^2, one warp per row.
// ---------------------------------------------------------------------------
__global__ void fsq_kernel() {
    const int warp = (blockIdx.x * blockDim.x + threadIdx.x) >> 5;
    const int lane = threadIdx.x & 31;
    if (warp >= NB * 256) return;
    const float* fr = g_f + (size_t)warp * 128;
    float s = 0.f;
#pragma unroll
    for (int d = 0; d < 4; d++) { float v = fr[lane + 32 * d]; s = fmaf(v, v, s); }
#pragma unroll
    for (int off = 16; off; off >>= 1) s += __shfl_down_sync(0xffffffffu, s, off);
    if (lane == 0) g_fsq[warp] = s;
}

// ---------------------------------------------------------------------------
// Prototype distances + partial min over 64 L-positions per block.
// Grid (4 chunks, B). Thread = prototype p. pt reads hit L1 (64 KB resident).
// ---------------------------------------------------------------------------
__global__ void __launch_bounds__(128) dist_kernel() {
    __shared__ float fs[8 * 128];
    const int b = blockIdx.y, chunk = blockIdx.x;
    const int p = threadIdx.x;
    const float psqv = g_psq[p];
    const float* fb = g_f   + ((size_t)(b * 256 + chunk * 64)) * 128;
    const float* fq = g_fsq + b * 256 + chunk * 64;
    float best = 3.4e38f;

    for (int l0 = 0; l0 < 64; l0 += 8) {
        __syncthreads();
        for (int i = p; i < 1024; i += 128) fs[i] = fb[(size_t)l0 * 128 + i];
        __syncthreads();
#pragma unroll 1
        for (int r = 0; r < 8; r++) {
            float dot = 0.f;
#pragma unroll 16
            for (int d = 0; d < 128; d++)
                dot = fmaf(g_pt[d * 128 + p], fs[r * 128 + d], dot);
            const float d2 = fq[l0 + r] - 2.f * dot + psqv;
            best = fminf(best, d2);
        }
    }
    g_minpart[(b * 4 + chunk) * 128 + p] = best;
}

// ---------------------------------------------------------------------------
// Final: combine partial mins, dis = sqrt(max(d2,1e-12)),
// sim = log((dis+1)/(dis+1e-4)), head = sigmoid(sim @ lw.T).
// Output layout: d_out[0:64] = out(32,2); d_out[64:4160] = min_dis(32,128).
// ---------------------------------------------------------------------------
__global__ void final_kernel(const int* __restrict__ classes, float* __restrict__ outp) {
    const int b = blockIdx.x, p = threadIdx.x;
    float m = g_minpart[(b * 4 + 0) * 128 + p];
    m = fminf(m, g_minpart[(b * 4 + 1) * 128 + p]);
    m = fminf(m, g_minpart[(b * 4 + 2) * 128 + p]);
    m = fminf(m, g_minpart[(b * 4 + 3) * 128 + p]);
    const float dis = sqrtf(fmaxf(m, 1e-12f));
    const float sim = logf((dis + 1.f) / (dis + 1e-4f));
    outp[64 + b * 128 + p] = dis;

    __shared__ float ss[128];
    ss[p] = sim;
    __syncthreads();
    if (p < 2) {
        float s = 0.f;
        for (int q = 0; q < 128; q++)
            s += ss[q] * ((classes[q] == p) ? 1.f : -0.5f);
        outp[b * 2 + p] = 1.f / (1.f + expf(-s));
    }
}

// ---------------------------------------------------------------------------
extern "C" void kernel_launch(void* const* d_in, const int* in_sizes, int n_in,
                              void* d_out, int out_size) {
    const float* x     = (const float*)d_in[0];
    const float* W1    = (const float*)d_in[1];
    const float* b1    = (const float*)d_in[2];
    const float* W2    = (const float*)d_in[3];
    const float* b2    = (const float*)d_in[4];
    const float* W3    = (const float*)d_in[5];
    const float* b3    = (const float*)d_in[6];
    const float* Wo1   = (const float*)d_in[7];
    const float* bo1   = (const float*)d_in[8];
    const float* Wo2   = (const float*)d_in[9];
    const float* bo2   = (const float*)d_in[10];
    const float* proto = (const float*)d_in[11];
    const int*   cls   = (const int*)d_in[12];
    float* out = (float*)d_out;
    (void)in_sizes; (void)n_in; (void)out_size;

    void *h1, *h2, *h3, *f, *w1t, *w2t, *w3t, *wo1t, *wo2t;
    cudaGetSymbolAddress(&h1, g_h1);
    cudaGetSymbolAddress(&h2, g_h2);
    cudaGetSymbolAddress(&h3, g_h3);
    cudaGetSymbolAddress(&f,  g_f);
    cudaGetSymbolAddress(&w1t, g_w1t);
    cudaGetSymbolAddress(&w2t, g_w2t);
    cudaGetSymbolAddress(&w3t, g_w3t);
    cudaGetSymbolAddress(&wo1t, g_wo1t);
    cudaGetSymbolAddress(&wo2t, g_wo2t);

    prep_kernel<<<256, 256>>>(W1, W2, W3, Wo1, Wo2, proto);

    conv_pool_kernel<76> <<<dim3(64, NB), 128>>>(x,           (const float*)w1t, b1, (float*)h1, 2048, 1024);
    conv_pool_kernel<128><<<dim3(32, NB), 128>>>((float*)h1,  (const float*)w2t, b2, (float*)h2, 1024, 512);
    conv_pool_kernel<128><<<dim3(16, NB), 128>>>((float*)h2,  (const float*)w3t, b3, (float*)h3, 512,  256);

    fc_kernel<<<dim3(16, NB), 128>>>((const float*)h3, (const float*)wo1t, bo1,
                                     (const float*)wo2t, bo2, (float*)f);
    fsq_kernel<<<1024, 256>>>();
    dist_kernel<<<dim3(4, NB), 128>>>();
    final_kernel<<<NB, 128>>>(cls, out);
}

// round 3
// speedup vs baseline: 1.5498x; 1.5498x over previous
#include <cuda_runtime.h>
#include <math.h>

// ---------------------------------------------------------------------------
// ProtICU: 3x(conv1d k=5 + relu + maxpool2) -> 2x 1x1 conv -> prototype L2
// distances -> min over patches -> log-sim -> sigmoid head.
//
// R2 changes (convs only):
//  * packed fma.rn.f32x2 over output-channel pairs (FFMA2, 2x fp32 rate)
//  * x tile stored duplicated (v,v) in SMEM -> broadcast operand is 1 LDS.64
//  * cp.async double-buffered weight prefetch, 1 barrier per 4-channel chunk
//  * 256 threads = 64 channel-pairs x 4 position-quarters (low reg pressure)
// ---------------------------------------------------------------------------

#define NB 32
typedef unsigned long long u64;

// Scratch (device globals: no allocation allowed in kernel_launch)
__device__ float g_h1[NB * 1024 * 128];
__device__ float g_h2[NB * 512 * 128];
__device__ float g_h3[NB * 256 * 128];
__device__ float g_f [NB * 256 * 128];
__device__ float g_fsq[NB * 256];
__device__ float g_w1t[76 * 5 * 128];
__device__ float g_w2t[128 * 5 * 128];
__device__ float g_w3t[128 * 5 * 128];
__device__ float g_wo1t[128 * 128];
__device__ float g_wo2t[128 * 128];
__device__ float g_pt[128 * 128];     // pt[d*128+p] = proto[p][d]
__device__ float g_psq[128];
__device__ float g_minpart[NB * 4 * 128];

__device__ __forceinline__ void ffma2(u64& d, u64 a, u64 b) {
    asm("fma.rn.f32x2 %0, %1, %2, %0;" : "+l"(d) : "l"(a), "l"(b));
}

// ---------------------------------------------------------------------------
// Prep: transpose all weights so the hot loops load coalesced.
//  w*t[(c*5+k)*128 + o] = W[o][c][k];  wo*t[c*128+o] = Wo[o][c];
//  pt[d*128+p] = proto[p][d];  psq[p] = ||proto[p]||^2
// ---------------------------------------------------------------------------
__global__ void prep_kernel(const float* __restrict__ W1, const float* __restrict__ W2,
                            const float* __restrict__ W3, const float* __restrict__ Wo1,
                            const float* __restrict__ Wo2, const float* __restrict__ proto) {
    const int stride = gridDim.x * blockDim.x;
    for (int i = blockIdx.x * blockDim.x + threadIdx.x; i < 128 * 5 * 128; i += stride) {
        const int o  = i & 127;
        const int ck = i >> 7;
        const int c = ck / 5, k = ck - 5 * c;
        if (i < 76 * 5 * 128) g_w1t[i] = W1[(o * 76 + c) * 5 + k];
        g_w2t[i] = W2[(o * 128 + c) * 5 + k];
        g_w3t[i] = W3[(o * 128 + c) * 5 + k];
        if (i < 128 * 128) {
            g_wo1t[i] = Wo1[o * 128 + ck];
            g_wo2t[i] = Wo2[o * 128 + ck];
            g_pt[i]   = proto[o * 128 + ck];  // i = d*128+p: o=p, ck=d
        }
        if (i < 128) {
            float s = 0.f;
            for (int d = 0; d < 128; d++) { float v = proto[i * 128 + d]; s = fmaf(v, v, s); }
            g_psq[i] = s;
        }
    }
}

// ---------------------------------------------------------------------------
// Fused conv1d(k=5, same) + ReLU + maxpool2, FFMA2 version.
// Block: 256 threads = 64 output-channel-pairs x 4 position-quarters.
// Tile: 32 pre-pool positions (16 pooled); each quarter owns 8 prepool.
// Weights double-buffered via cp.async (one barrier per 4-channel chunk).
// SMEM: ws[2][4*5*128] floats, xs2[CIN*36] float2 (x duplicated (v,v)).
// ---------------------------------------------------------------------------
template <int CIN>
__global__ void __launch_bounds__(256)
conv_pool_v2(const float* __restrict__ in, const float* __restrict__ wt,
             const float* __restrict__ bias, float* __restrict__ out,
             int Lin, int Lpool) {
    constexpr int TPRE = 32;
    constexpr int XS   = TPRE + 4;   // 36
    constexpr int NCH  = CIN / 4;
    extern __shared__ char smem[];
    float*  ws  = (float*)smem;                        // 2 x 2560 floats
    float2* xs2 = (float2*)(smem + 2 * 2560 * 4);      // CIN*XS float2

    const int tid = threadIdx.x;
    const int op  = tid & 63;     // output-channel pair: channels 2op, 2op+1
    const int q   = tid >> 6;     // position quarter 0..3
    const int jb  = q * 8;
    const int b   = blockIdx.y;
    const int l0  = blockIdx.x * TPRE;

    const unsigned ws_base = (unsigned)__cvta_generic_to_shared(ws);

    // prefetch chunk 0 weights (2560 floats = 640 x 16B)
    for (int i = tid; i < 640; i += 256) {
        asm volatile("cp.async.ca.shared.global [%0], [%1], 16;"
                     :: "r"(ws_base + i * 16), "l"(wt + i * 4));
    }
    asm volatile("cp.async.commit_group;" ::: "memory");

    // x tile, duplicated (v,v) so the broadcast FFMA2 operand is one LDS.64
    const float* inb = in + (size_t)b * Lin * CIN;
    for (int i = tid; i < XS * CIN; i += 256) {
        const int pos = i / CIN;
        const int c   = i - pos * CIN;
        const int l   = l0 - 2 + pos;
        const float v = (l >= 0 && l < Lin) ? inb[(size_t)l * CIN + c] : 0.f;
        xs2[c * XS + pos] = make_float2(v, v);
    }

    u64 acc[8];
    {
        const float2 bv = *(const float2*)(bias + 2 * op);
        u64 bp;
        asm("mov.b64 %0, {%1,%2};" : "=l"(bp) : "f"(bv.x), "f"(bv.y));
#pragma unroll
        for (int j = 0; j < 8; j++) acc[j] = bp;
    }

    for (int ch = 0; ch < NCH; ch++) {
        asm volatile("cp.async.wait_group 0;" ::: "memory");
        __syncthreads();   // chunk ch data visible; compute(ch-1) done everywhere
        if (ch + 1 < NCH) {
            const float*   src = wt + (ch + 1) * 2560;
            const unsigned dst = ws_base + ((ch + 1) & 1) * 10240;
            for (int i = tid; i < 640; i += 256) {
                asm volatile("cp.async.ca.shared.global [%0], [%1], 16;"
                             :: "r"(dst + i * 16), "l"(src + i * 4));
            }
            asm volatile("cp.async.commit_group;" ::: "memory");
        }
        const float* wbuf = ws + (ch & 1) * 2560;
        const int c0 = ch * 4;
#pragma unroll
        for (int cc = 0; cc < 4; cc++) {
            const float2* xc = xs2 + (c0 + cc) * XS + jb;
            u64 xr[12];
#pragma unroll
            for (int p = 0; p < 12; p++) xr[p] = *(const u64*)(xc + p);
#pragma unroll
            for (int k = 0; k < 5; k++) {
                const u64 w2 = *(const u64*)(wbuf + (cc * 5 + k) * 128 + 2 * op);
#pragma unroll
                for (int j = 0; j < 8; j++) ffma2(acc[j], w2, xr[j + k]);
            }
        }
    }

    // relu + maxpool2 + store (float2, coalesced over channel pairs)
    float* outb = out + ((size_t)b * Lpool + l0 / 2 + jb / 2) * 128 + 2 * op;
#pragma unroll
    for (int m = 0; m < 4; m++) {
        const float2 a0 = *(const float2*)&acc[2 * m];
        const float2 a1 = *(const float2*)&acc[2 * m + 1];
        float2 r;
        r.x = fmaxf(fmaxf(a0.x, a1.x), 0.f);
        r.y = fmaxf(fmaxf(a0.y, a1.y), 0.f);
        *(float2*)(outb + (size_t)m * 128) = r;
    }
}

// ---------------------------------------------------------------------------
// Two fused 1x1 convs (channel matmuls) with ReLU.
// Block: 128 threads = out channel, tile of 16 L-rows.
// ---------------------------------------------------------------------------
__global__ void __launch_bounds__(128)
fc_kernel(const float* __restrict__ in, const float* __restrict__ w1t,
          const float* __restrict__ b1, const float* __restrict__ w2t,
          const float* __restrict__ b2, float* __restrict__ f) {
    __shared__ float hs[16 * 128];
    __shared__ float ws[16 * 128];
    __shared__ float ms[16 * 128];

    const int b    = blockIdx.y;
    const int row0 = blockIdx.x * 16;
    const int o    = threadIdx.x;

    const float* inb = in + ((size_t)b * 256 + row0) * 128;
    for (int i = o; i < 2048; i += 128) hs[i] = inb[i];

    float acc[16];
    float bv = b1[o];
#pragma unroll
    for (int j = 0; j < 16; j++) acc[j] = bv;

    for (int c0 = 0; c0 < 128; c0 += 16) {
        __syncthreads();
        for (int i = o; i < 2048; i += 128) ws[i] = w1t[c0 * 128 + i];
        __syncthreads();
#pragma unroll
        for (int cc = 0; cc < 16; cc++) {
            const float wv = ws[cc * 128 + o];
#pragma unroll
            for (int j = 0; j < 16; j++) acc[j] = fmaf(wv, hs[j * 128 + c0 + cc], acc[j]);
        }
    }
    __syncthreads();
#pragma unroll
    for (int j = 0; j < 16; j++) ms[j * 128 + o] = fmaxf(acc[j], 0.f);

    bv = b2[o];
#pragma unroll
    for (int j = 0; j < 16; j++) acc[j] = bv;

    for (int c0 = 0; c0 < 128; c0 += 16) {
        __syncthreads();
        for (int i = o; i < 2048; i += 128) ws[i] = w2t[c0 * 128 + i];
        __syncthreads();
#pragma unroll
        for (int cc = 0; cc < 16; cc++) {
            const float wv = ws[cc * 128 + o];
#pragma unroll
            for (int j = 0; j < 16; j++) acc[j] = fmaf(wv, ms[j * 128 + c0 + cc], acc[j]);
        }
    }

    float* fb = f + ((size_t)b * 256 + row0) * 128;
#pragma unroll
    for (int j = 0; j < 16; j++) fb[j * 128 + o] = fmaxf(acc[j], 0.f);
}

// ---------------------------------------------------------------------------
// fsq[row] = ||f_row||^2, one warp per row.
// ---------------------------------------------------------------------------
__global__ void fsq_kernel() {
    const int warp = (blockIdx.x * blockDim.x + threadIdx.x) >> 5;
    const int lane = threadIdx.x & 31;
    if (warp >= NB * 256) return;
    const float* fr = g_f + (size_t)warp * 128;
    float s = 0.f;
#pragma unroll
    for (int d = 0; d < 4; d++) { float v = fr[lane + 32 * d]; s = fmaf(v, v, s); }
#pragma unroll
    for (int off = 16; off; off >>= 1) s += __shfl_down_sync(0xffffffffu, s, off);
    if (lane == 0) g_fsq[warp] = s;
}

// ---------------------------------------------------------------------------
// Prototype distances + partial min over 64 L-positions per block.
// ---------------------------------------------------------------------------
__global__ void __launch_bounds__(128) dist_kernel() {
    __shared__ float fs[8 * 128];
    const int b = blockIdx.y, chunk = blockIdx.x;
    const int p = threadIdx.x;
    const float psqv = g_psq[p];
    const float* fb = g_f   + ((size_t)(b * 256 + chunk * 64)) * 128;
    const float* fq = g_fsq + b * 256 + chunk * 64;
    float best = 3.4e38f;

    for (int l0 = 0; l0 < 64; l0 += 8) {
        __syncthreads();
        for (int i = p; i < 1024; i += 128) fs[i] = fb[(size_t)l0 * 128 + i];
        __syncthreads();
#pragma unroll 1
        for (int r = 0; r < 8; r++) {
            float dot = 0.f;
#pragma unroll 16
            for (int d = 0; d < 128; d++)
                dot = fmaf(g_pt[d * 128 + p], fs[r * 128 + d], dot);
            const float d2 = fq[l0 + r] - 2.f * dot + psqv;
            best = fminf(best, d2);
        }
    }
    g_minpart[(b * 4 + chunk) * 128 + p] = best;
}

// ---------------------------------------------------------------------------
// Final: combine partial mins, dis = sqrt(max(d2,1e-12)),
// sim = log((dis+1)/(dis+1e-4)), head = sigmoid(sim @ lw.T).
// Output layout: d_out[0:64] = out(32,2); d_out[64:4160] = min_dis(32,128).
// ---------------------------------------------------------------------------
__global__ void final_kernel(const int* __restrict__ classes, float* __restrict__ outp) {
    const int b = blockIdx.x, p = threadIdx.x;
    float m = g_minpart[(b * 4 + 0) * 128 + p];
    m = fminf(m, g_minpart[(b * 4 + 1) * 128 + p]);
    m = fminf(m, g_minpart[(b * 4 + 2) * 128 + p]);
    m = fminf(m, g_minpart[(b * 4 + 3) * 128 + p]);
    const float dis = sqrtf(fmaxf(m, 1e-12f));
    const float sim = logf((dis + 1.f) / (dis + 1e-4f));
    outp[64 + b * 128 + p] = dis;

    __shared__ float ss[128];
    ss[p] = sim;
    __syncthreads();
    if (p < 2) {
        float s = 0.f;
        for (int q = 0; q < 128; q++)
            s += ss[q] * ((classes[q] == p) ? 1.f : -0.5f);
        outp[b * 2 + p] = 1.f / (1.f + expf(-s));
    }
}

// ---------------------------------------------------------------------------
extern "C" void kernel_launch(void* const* d_in, const int* in_sizes, int n_in,
                              void* d_out, int out_size) {
    const float* x     = (const float*)d_in[0];
    const float* W1    = (const float*)d_in[1];
    const float* b1    = (const float*)d_in[2];
    const float* W2    = (const float*)d_in[3];
    const float* b2    = (const float*)d_in[4];
    const float* W3    = (const float*)d_in[5];
    const float* b3    = (const float*)d_in[6];
    const float* Wo1   = (const float*)d_in[7];
    const float* bo1   = (const float*)d_in[8];
    const float* Wo2   = (const float*)d_in[9];
    const float* bo2   = (const float*)d_in[10];
    const float* proto = (const float*)d_in[11];
    const int*   cls   = (const int*)d_in[12];
    float* out = (float*)d_out;
    (void)in_sizes; (void)n_in; (void)out_size;

    void *h1, *h2, *h3, *f, *w1t, *w2t, *w3t, *wo1t, *wo2t;
    cudaGetSymbolAddress(&h1, g_h1);
    cudaGetSymbolAddress(&h2, g_h2);
    cudaGetSymbolAddress(&h3, g_h3);
    cudaGetSymbolAddress(&f,  g_f);
    cudaGetSymbolAddress(&w1t, g_w1t);
    cudaGetSymbolAddress(&w2t, g_w2t);
    cudaGetSymbolAddress(&w3t, g_w3t);
    cudaGetSymbolAddress(&wo1t, g_wo1t);
    cudaGetSymbolAddress(&wo2t, g_wo2t);

    const int smem76  = 2 * 2560 * 4 + 76  * 36 * 8;   // 42368
    const int smem128 = 2 * 2560 * 4 + 128 * 36 * 8;   // 57344
    cudaFuncSetAttribute(conv_pool_v2<76>,  cudaFuncAttributeMaxDynamicSharedMemorySize, smem76);
    cudaFuncSetAttribute(conv_pool_v2<128>, cudaFuncAttributeMaxDynamicSharedMemorySize, smem128);

    prep_kernel<<<256, 256>>>(W1, W2, W3, Wo1, Wo2, proto);

    conv_pool_v2<76> <<<dim3(64, NB), 256, smem76 >>>(x,          (const float*)w1t, b1, (float*)h1, 2048, 1024);
    conv_pool_v2<128><<<dim3(32, NB), 256, smem128>>>((float*)h1, (const float*)w2t, b2, (float*)h2, 1024, 512);
    conv_pool_v2<128><<<dim3(16, NB), 256, smem128>>>((float*)h2, (const float*)w3t, b3, (float*)h3, 512,  256);

    fc_kernel<<<dim3(16, NB), 128>>>((const float*)h3, (const float*)wo1t, bo1,
                                     (const float*)wo2t, bo2, (float*)f);
    fsq_kernel<<<1024, 256>>>();
    dist_kernel<<<dim3(4, NB), 128>>>();
    final_kernel<<<NB, 128>>>(cls, out);
}

// round 4
// speedup vs baseline: 1.8415x; 1.1882x over previous
#include <cuda_runtime.h>
#include <math.h>

// ---------------------------------------------------------------------------
// ProtICU R4: FFMA2 everywhere, 2x output-channel register blocking in convs,
// fused fc(2 layers)+fsq, SMEM-resident prototypes in dist.
// ---------------------------------------------------------------------------

#define NB 32
typedef unsigned long long u64;

__device__ float g_h1[NB * 1024 * 128];
__device__ float g_h2[NB * 512 * 128];
__device__ float g_h3[NB * 256 * 128];
__device__ float g_f [NB * 256 * 128];
__device__ float g_fsq[NB * 256];
__device__ float g_w1t[76 * 5 * 128];
__device__ float g_w2t[128 * 5 * 128];
__device__ float g_w3t[128 * 5 * 128];
__device__ float g_wo1t[128 * 128];
__device__ float g_wo2t[128 * 128];
__device__ float g_psq[128];
__device__ float g_minpart[NB * 4 * 128];

__device__ __forceinline__ void ffma2(u64& d, u64 a, u64 b) {
    asm("fma.rn.f32x2 %0, %1, %2, %0;" : "+l"(d) : "l"(a), "l"(b));
}

// ---------------------------------------------------------------------------
// Prep: transposed weights. w*t[(c*5+k)*128+o]=W[o][c][k]; wo*t[c*128+o]=Wo[o][c]
// ---------------------------------------------------------------------------
__global__ void prep_kernel(const float* __restrict__ W1, const float* __restrict__ W2,
                            const float* __restrict__ W3, const float* __restrict__ Wo1,
                            const float* __restrict__ Wo2, const float* __restrict__ proto) {
    const int stride = gridDim.x * blockDim.x;
    for (int i = blockIdx.x * blockDim.x + threadIdx.x; i < 128 * 5 * 128; i += stride) {
        const int o  = i & 127;
        const int ck = i >> 7;
        const int c = ck / 5, k = ck - 5 * c;
        if (i < 76 * 5 * 128) g_w1t[i] = W1[(o * 76 + c) * 5 + k];
        g_w2t[i] = W2[(o * 128 + c) * 5 + k];
        g_w3t[i] = W3[(o * 128 + c) * 5 + k];
        if (i < 128 * 128) {
            g_wo1t[i] = Wo1[o * 128 + ck];
            g_wo2t[i] = Wo2[o * 128 + ck];
        }
        if (i < 128) {
            float s = 0.f;
            for (int d = 0; d < 128; d++) { float v = proto[i * 128 + d]; s = fmaf(v, v, s); }
            g_psq[i] = s;
        }
    }
}

// ---------------------------------------------------------------------------
// Conv1d(k=5,same)+ReLU+maxpool2. 128 threads = 32 op x 4 quarters.
// Each thread: 2 channel pairs {2op,2op+1} and {64+2op,65+2op} x 8 prepool pos.
// cp.async double-buffered weights; x duplicated (v,v) for broadcast LDS.64.
// ---------------------------------------------------------------------------
template <int CIN>
__global__ void __launch_bounds__(128)
conv_pool_v3(const float* __restrict__ in, const float* __restrict__ wt,
             const float* __restrict__ bias, float* __restrict__ out,
             int Lin, int Lpool) {
    constexpr int TPRE = 32;
    constexpr int XS   = TPRE + 4;   // 36
    constexpr int NCH  = CIN / 4;
    extern __shared__ char smem[];
    float*  ws  = (float*)smem;                        // 2 x 2560 floats
    float2* xs2 = (float2*)(smem + 2 * 2560 * 4);      // CIN*XS float2 (dup)

    const int tid = threadIdx.x;
    const int op  = tid & 31;
    const int q   = tid >> 5;
    const int jb  = q * 8;
    const int b   = blockIdx.y;
    const int l0  = blockIdx.x * TPRE;

    const unsigned ws_base = (unsigned)__cvta_generic_to_shared(ws);

    for (int i = tid; i < 640; i += 128) {
        asm volatile("cp.async.ca.shared.global [%0], [%1], 16;"
                     :: "r"(ws_base + i * 16), "l"(wt + i * 4));
    }
    asm volatile("cp.async.commit_group;" ::: "memory");

    const float* inb = in + (size_t)b * Lin * CIN;
    for (int i = tid; i < XS * CIN; i += 128) {
        const int pos = i / CIN;
        const int c   = i - pos * CIN;
        const int l   = l0 - 2 + pos;
        const float v = (l >= 0 && l < Lin) ? inb[(size_t)l * CIN + c] : 0.f;
        xs2[c * XS + pos] = make_float2(v, v);
    }

    u64 accA[8], accB[8];
    {
        const float2 ba = *(const float2*)(bias + 2 * op);
        const float2 bb = *(const float2*)(bias + 64 + 2 * op);
        u64 pa, pb;
        asm("mov.b64 %0, {%1,%2};" : "=l"(pa) : "f"(ba.x), "f"(ba.y));
        asm("mov.b64 %0, {%1,%2};" : "=l"(pb) : "f"(bb.x), "f"(bb.y));
#pragma unroll
        for (int j = 0; j < 8; j++) { accA[j] = pa; accB[j] = pb; }
    }

    for (int ch = 0; ch < NCH; ch++) {
        asm volatile("cp.async.wait_group 0;" ::: "memory");
        __syncthreads();
        if (ch + 1 < NCH) {
            const float*   src = wt + (ch + 1) * 2560;
            const unsigned dst = ws_base + ((ch + 1) & 1) * 10240;
            for (int i = tid; i < 640; i += 128) {
                asm volatile("cp.async.ca.shared.global [%0], [%1], 16;"
                             :: "r"(dst + i * 16), "l"(src + i * 4));
            }
            asm volatile("cp.async.commit_group;" ::: "memory");
        }
        const float* wbuf = ws + (ch & 1) * 2560;
        const int c0 = ch * 4;
#pragma unroll
        for (int cc = 0; cc < 4; cc++) {
            const float2* xc = xs2 + (c0 + cc) * XS + jb;
            u64 xr[12];
#pragma unroll
            for (int p = 0; p < 12; p++) xr[p] = *(const u64*)(xc + p);
#pragma unroll
            for (int k = 0; k < 5; k++) {
                const float* wrow = wbuf + (cc * 5 + k) * 128;
                const u64 wa = *(const u64*)(wrow + 2 * op);
                const u64 wb = *(const u64*)(wrow + 64 + 2 * op);
#pragma unroll
                for (int j = 0; j < 8; j++) {
                    ffma2(accA[j], wa, xr[j + k]);
                    ffma2(accB[j], wb, xr[j + k]);
                }
            }
        }
    }

    float* outb = out + ((size_t)b * Lpool + l0 / 2 + jb / 2) * 128;
#pragma unroll
    for (int m = 0; m < 4; m++) {
        const float2 a0 = *(const float2*)&accA[2 * m];
        const float2 a1 = *(const float2*)&accA[2 * m + 1];
        const float2 b0 = *(const float2*)&accB[2 * m];
        const float2 b1 = *(const float2*)&accB[2 * m + 1];
        float2 ra, rb;
        ra.x = fmaxf(fmaxf(a0.x, a1.x), 0.f);
        ra.y = fmaxf(fmaxf(a0.y, a1.y), 0.f);
        rb.x = fmaxf(fmaxf(b0.x, b1.x), 0.f);
        rb.y = fmaxf(fmaxf(b0.y, b1.y), 0.f);
        *(float2*)(outb + (size_t)m * 128 + 2 * op)      = ra;
        *(float2*)(outb + (size_t)m * 128 + 64 + 2 * op) = rb;
    }
}

// ---------------------------------------------------------------------------
// Fused 1x1 convs (2 layers) + ReLU + fsq. 128 threads = 32 op x 4 quarters,
// tile = 32 L-rows. Each thread: 2 channel pairs x 8 rows. Inputs staged
// duplicated (v,v); weights cp.async double-buffered in 16-ch chunks.
// ---------------------------------------------------------------------------
__global__ void __launch_bounds__(128)
fc_fused(const float* __restrict__ in, const float* __restrict__ w1t,
         const float* __restrict__ b1, const float* __restrict__ w2t,
         const float* __restrict__ b2, float* __restrict__ f,
         float* __restrict__ fsq) {
    extern __shared__ char smem[];
    float*  ws  = (float*)smem;                          // 2 x 2048 floats
    float2* hs2 = (float2*)(smem + 16384);               // [c*33 + r], 33792 B
    float2* ms2 = (float2*)(smem + 16384 + 33792);       // same

    const int tid  = threadIdx.x;
    const int op   = tid & 31;
    const int q    = tid >> 5;
    const int b    = blockIdx.y;
    const int row0 = blockIdx.x * 32;
    const unsigned ws_base = (unsigned)__cvta_generic_to_shared(ws);

    for (int i = tid; i < 512; i += 128) {
        asm volatile("cp.async.ca.shared.global [%0], [%1], 16;"
                     :: "r"(ws_base + i * 16), "l"(w1t + i * 4));
    }
    asm volatile("cp.async.commit_group;" ::: "memory");

    const float* inb = in + ((size_t)b * 256 + row0) * 128;
    for (int i = tid; i < 32 * 128; i += 128) {
        const int r = i >> 7, c = i & 127;
        const float v = inb[i];
        hs2[c * 33 + r] = make_float2(v, v);
    }

    u64 accA[8], accB[8];
    u64 pa, pb;
    {
        const float2 ba = *(const float2*)(b1 + 2 * op);
        const float2 bb = *(const float2*)(b1 + 64 + 2 * op);
        asm("mov.b64 %0, {%1,%2};" : "=l"(pa) : "f"(ba.x), "f"(ba.y));
        asm("mov.b64 %0, {%1,%2};" : "=l"(pb) : "f"(bb.x), "f"(bb.y));
#pragma unroll
        for (int j = 0; j < 8; j++) { accA[j] = pa; accB[j] = pb; }
    }

    // ---- layer 1 ----
    for (int c0 = 0; c0 < 8; c0++) {
        asm volatile("cp.async.wait_group 0;" ::: "memory");
        __syncthreads();
        if (c0 + 1 < 8) {
            const float*   src = w1t + (c0 + 1) * 2048;
            const unsigned dst = ws_base + ((c0 + 1) & 1) * 8192;
            for (int i = tid; i < 512; i += 128) {
                asm volatile("cp.async.ca.shared.global [%0], [%1], 16;"
                             :: "r"(dst + i * 16), "l"(src + i * 4));
            }
            asm volatile("cp.async.commit_group;" ::: "memory");
        }
        const float* wbuf = ws + (c0 & 1) * 2048;
#pragma unroll
        for (int cc = 0; cc < 16; cc++) {
            const u64 wa = *(const u64*)(wbuf + cc * 128 + 2 * op);
            const u64 wb = *(const u64*)(wbuf + cc * 128 + 64 + 2 * op);
            const float2* xb = hs2 + (c0 * 16 + cc) * 33 + q * 8;
#pragma unroll
            for (int j = 0; j < 8; j++) {
                const u64 x = *(const u64*)(xb + j);
                ffma2(accA[j], wa, x);
                ffma2(accB[j], wb, x);
            }
        }
    }

    // prefetch layer-2 chunk 0 (all threads past last wait; ws[0] free)
    __syncthreads();
    for (int i = tid; i < 512; i += 128) {
        asm volatile("cp.async.ca.shared.global [%0], [%1], 16;"
                     :: "r"(ws_base + i * 16), "l"(w2t + i * 4));
    }
    asm volatile("cp.async.commit_group;" ::: "memory");

    // relu -> ms2 (dup)
#pragma unroll
    for (int j = 0; j < 8; j++) {
        float2 a = *(const float2*)&accA[j];
        float2 c = *(const float2*)&accB[j];
        a.x = fmaxf(a.x, 0.f); a.y = fmaxf(a.y, 0.f);
        c.x = fmaxf(c.x, 0.f); c.y = fmaxf(c.y, 0.f);
        const int r = q * 8 + j;
        ms2[(2 * op)     * 33 + r] = make_float2(a.x, a.x);
        ms2[(2 * op + 1) * 33 + r] = make_float2(a.y, a.y);
        ms2[(64 + 2 * op)     * 33 + r] = make_float2(c.x, c.x);
        ms2[(64 + 2 * op + 1) * 33 + r] = make_float2(c.y, c.y);
    }

    {
        const float2 ba = *(const float2*)(b2 + 2 * op);
        const float2 bb = *(const float2*)(b2 + 64 + 2 * op);
        asm("mov.b64 %0, {%1,%2};" : "=l"(pa) : "f"(ba.x), "f"(ba.y));
        asm("mov.b64 %0, {%1,%2};" : "=l"(pb) : "f"(bb.x), "f"(bb.y));
#pragma unroll
        for (int j = 0; j < 8; j++) { accA[j] = pa; accB[j] = pb; }
    }

    // ---- layer 2 ----
    for (int c0 = 0; c0 < 8; c0++) {
        asm volatile("cp.async.wait_group 0;" ::: "memory");
        __syncthreads();
        if (c0 + 1 < 8) {
            const float*   src = w2t + (c0 + 1) * 2048;
            const unsigned dst = ws_base + ((c0 + 1) & 1) * 8192;
            for (int i = tid; i < 512; i += 128) {
                asm volatile("cp.async.ca.shared.global [%0], [%1], 16;"
                             :: "r"(dst + i * 16), "l"(src + i * 4));
            }
            asm volatile("cp.async.commit_group;" ::: "memory");
        }
        const float* wbuf = ws + (c0 & 1) * 2048;
#pragma unroll
        for (int cc = 0; cc < 16; cc++) {
            const u64 wa = *(const u64*)(wbuf + cc * 128 + 2 * op);
            const u64 wb = *(const u64*)(wbuf + cc * 128 + 64 + 2 * op);
            const float2* xb = ms2 + (c0 * 16 + cc) * 33 + q * 8;
#pragma unroll
            for (int j = 0; j < 8; j++) {
                const u64 x = *(const u64*)(xb + j);
                ffma2(accA[j], wa, x);
                ffma2(accB[j], wb, x);
            }
        }
    }

    // relu + store f + fused fsq (warp covers all 128 channels)
    float* fb = f + ((size_t)b * 256 + row0 + q * 8) * 128;
#pragma unroll
    for (int j = 0; j < 8; j++) {
        float2 a = *(const float2*)&accA[j];
        float2 c = *(const float2*)&accB[j];
        a.x = fmaxf(a.x, 0.f); a.y = fmaxf(a.y, 0.f);
        c.x = fmaxf(c.x, 0.f); c.y = fmaxf(c.y, 0.f);
        *(float2*)(fb + (size_t)j * 128 + 2 * op)      = a;
        *(float2*)(fb + (size_t)j * 128 + 64 + 2 * op) = c;
        float s = a.x * a.x + a.y * a.y + c.x * c.x + c.y * c.y;
#pragma unroll
        for (int off = 16; off; off >>= 1) s += __shfl_down_sync(0xffffffffu, s, off);
        if (op == 0) fsq[(size_t)b * 256 + row0 + q * 8 + j] = s;
    }
}

// ---------------------------------------------------------------------------
// Prototype L2 distances + partial min over 64 rows per block.
// Prototypes staged to SMEM once (stride 130 floats, 2-way conflicts max).
// FFMA2 over d-pairs; fs loads are warp-broadcast.
// ---------------------------------------------------------------------------
__global__ void __launch_bounds__(128)
dist_v2(const float* __restrict__ proto) {
    extern __shared__ char smem[];
    float* protoS = (float*)smem;                 // [p*130 + d], 66560 B
    float* fs     = (float*)(smem + 66560);       // [r*128 + d], 4096 B

    const int b = blockIdx.y, chunk = blockIdx.x;
    const int p = threadIdx.x;

    for (int i = p; i < 128 * 128; i += 128) {
        const int pp = i >> 7, d = i & 127;
        protoS[pp * 130 + d] = proto[i];
    }
    const float psqv = g_psq[p];
    const float* fb = g_f   + ((size_t)(b * 256 + chunk * 64)) * 128;
    const float* fq = g_fsq + b * 256 + chunk * 64;
    float best = 3.4e38f;

    for (int l0 = 0; l0 < 64; l0 += 8) {
        __syncthreads();
        for (int i = p; i < 1024; i += 128) fs[i] = fb[(size_t)l0 * 128 + i];
        __syncthreads();

        u64 acc2[8];
#pragma unroll
        for (int r = 0; r < 8; r++) acc2[r] = 0ull;
#pragma unroll
        for (int dc = 0; dc < 4; dc++) {
            u64 ptr_[16];
#pragma unroll
            for (int i = 0; i < 16; i++)
                ptr_[i] = *(const u64*)(protoS + p * 130 + dc * 32 + 2 * i);
#pragma unroll
            for (int r = 0; r < 8; r++) {
                const float* fr = fs + r * 128 + dc * 32;
#pragma unroll
                for (int i = 0; i < 16; i++)
                    ffma2(acc2[r], ptr_[i], *(const u64*)(fr + 2 * i));
            }
        }
#pragma unroll
        for (int r = 0; r < 8; r++) {
            const float2 a = *(const float2*)&acc2[r];
            const float dot = a.x + a.y;
            const float d2 = fq[l0 + r] - 2.f * dot + psqv;
            best = fminf(best, d2);
        }
    }
    g_minpart[(b * 4 + chunk) * 128 + p] = best;
}

// ---------------------------------------------------------------------------
// Final head.  d_out[0:64] = out(32,2); d_out[64:4160] = min_dis(32,128).
// ---------------------------------------------------------------------------
__global__ void final_kernel(const int* __restrict__ classes, float* __restrict__ outp) {
    const int b = blockIdx.x, p = threadIdx.x;
    float m = g_minpart[(b * 4 + 0) * 128 + p];
    m = fminf(m, g_minpart[(b * 4 + 1) * 128 + p]);
    m = fminf(m, g_minpart[(b * 4 + 2) * 128 + p]);
    m = fminf(m, g_minpart[(b * 4 + 3) * 128 + p]);
    const float dis = sqrtf(fmaxf(m, 1e-12f));
    const float sim = logf((dis + 1.f) / (dis + 1e-4f));
    outp[64 + b * 128 + p] = dis;

    __shared__ float ss[128];
    ss[p] = sim;
    __syncthreads();
    if (p < 2) {
        float s = 0.f;
        for (int q = 0; q < 128; q++)
            s += ss[q] * ((classes[q] == p) ? 1.f : -0.5f);
        outp[b * 2 + p] = 1.f / (1.f + expf(-s));
    }
}

// ---------------------------------------------------------------------------
extern "C" void kernel_launch(void* const* d_in, const int* in_sizes, int n_in,
                              void* d_out, int out_size) {
    const float* x     = (const float*)d_in[0];
    const float* W1    = (const float*)d_in[1];
    const float* b1    = (const float*)d_in[2];
    const float* W2    = (const float*)d_in[3];
    const float* b2    = (const float*)d_in[4];
    const float* W3    = (const float*)d_in[5];
    const float* b3    = (const float*)d_in[6];
    const float* Wo1   = (const float*)d_in[7];
    const float* bo1   = (const float*)d_in[8];
    const float* Wo2   = (const float*)d_in[9];
    const float* bo2   = (const float*)d_in[10];
    const float* proto = (const float*)d_in[11];
    const int*   cls   = (const int*)d_in[12];
    float* out = (float*)d_out;
    (void)in_sizes; (void)n_in; (void)out_size;

    void *h1, *h2, *h3, *f, *fsq, *w1t, *w2t, *w3t, *wo1t, *wo2t;
    cudaGetSymbolAddress(&h1, g_h1);
    cudaGetSymbolAddress(&h2, g_h2);
    cudaGetSymbolAddress(&h3, g_h3);
    cudaGetSymbolAddress(&f,  g_f);
    cudaGetSymbolAddress(&fsq, g_fsq);
    cudaGetSymbolAddress(&w1t, g_w1t);
    cudaGetSymbolAddress(&w2t, g_w2t);
    cudaGetSymbolAddress(&w3t, g_w3t);
    cudaGetSymbolAddress(&wo1t, g_wo1t);
    cudaGetSymbolAddress(&wo2t, g_wo2t);

    const int smem76  = 2 * 2560 * 4 + 76  * 36 * 8;   // 42368
    const int smem128 = 2 * 2560 * 4 + 128 * 36 * 8;   // 57344
    const int smemfc  = 16384 + 2 * 33792;             // 83968
    const int smemd   = 66560 + 4096;                  // 70656
    cudaFuncSetAttribute(conv_pool_v3<76>,  cudaFuncAttributeMaxDynamicSharedMemorySize, smem76);
    cudaFuncSetAttribute(conv_pool_v3<128>, cudaFuncAttributeMaxDynamicSharedMemorySize, smem128);
    cudaFuncSetAttribute(fc_fused, cudaFuncAttributeMaxDynamicSharedMemorySize, smemfc);
    cudaFuncSetAttribute(dist_v2,  cudaFuncAttributeMaxDynamicSharedMemorySize, smemd);

    prep_kernel<<<256, 256>>>(W1, W2, W3, Wo1, Wo2, proto);

    conv_pool_v3<76> <<<dim3(64, NB), 128, smem76 >>>(x,          (const float*)w1t, b1, (float*)h1, 2048, 1024);
    conv_pool_v3<128><<<dim3(32, NB), 128, smem128>>>((float*)h1, (const float*)w2t, b2, (float*)h2, 1024, 512);
    conv_pool_v3<128><<<dim3(16, NB), 128, smem128>>>((float*)h2, (const float*)w3t, b3, (float*)h3, 512,  256);

    fc_fused<<<dim3(8, NB), 128, smemfc>>>((const float*)h3, (const float*)wo1t, bo1,
                                           (const float*)wo2t, bo2, (float*)f, (float*)fsq);
    dist_v2<<<dim3(4, NB), 128, smemd>>>(proto);
    final_kernel<<<NB, 128>>>(cls, out);
}

// round 5
// speedup vs baseline: 2.1353x; 1.1595x over previous
#include <cuda_runtime.h>
#include <math.h>

// ---------------------------------------------------------------------------
// ProtICU R5: conv x-tile stored plain (not duplicated); (v,v) FFMA2 operand
// built with mov.b64 {v,v}. Smem/CTA drops ~57->39 KB => 5-7 CTAs/SM.
// ---------------------------------------------------------------------------

#define NB 32
typedef unsigned long long u64;

__device__ float g_h1[NB * 1024 * 128];
__device__ float g_h2[NB * 512 * 128];
__device__ float g_h3[NB * 256 * 128];
__device__ float g_f [NB * 256 * 128];
__device__ float g_fsq[NB * 256];
__device__ float g_w1t[76 * 5 * 128];
__device__ float g_w2t[128 * 5 * 128];
__device__ float g_w3t[128 * 5 * 128];
__device__ float g_wo1t[128 * 128];
__device__ float g_wo2t[128 * 128];
__device__ float g_psq[128];
__device__ float g_minpart[NB * 4 * 128];

__device__ __forceinline__ void ffma2(u64& d, u64 a, u64 b) {
    asm("fma.rn.f32x2 %0, %1, %2, %0;" : "+l"(d) : "l"(a), "l"(b));
}
__device__ __forceinline__ u64 dup2(float v) {
    u64 r;
    asm("mov.b64 %0, {%1, %1};" : "=l"(r) : "f"(v));
    return r;
}

// ---------------------------------------------------------------------------
// Prep: transposed weights. w*t[(c*5+k)*128+o]=W[o][c][k]; wo*t[c*128+o]=Wo[o][c]
// ---------------------------------------------------------------------------
__global__ void prep_kernel(const float* __restrict__ W1, const float* __restrict__ W2,
                            const float* __restrict__ W3, const float* __restrict__ Wo1,
                            const float* __restrict__ Wo2, const float* __restrict__ proto) {
    const int stride = gridDim.x * blockDim.x;
    for (int i = blockIdx.x * blockDim.x + threadIdx.x; i < 128 * 5 * 128; i += stride) {
        const int o  = i & 127;
        const int ck = i >> 7;
        const int c = ck / 5, k = ck - 5 * c;
        if (i < 76 * 5 * 128) g_w1t[i] = W1[(o * 76 + c) * 5 + k];
        g_w2t[i] = W2[(o * 128 + c) * 5 + k];
        g_w3t[i] = W3[(o * 128 + c) * 5 + k];
        if (i < 128 * 128) {
            g_wo1t[i] = Wo1[o * 128 + ck];
            g_wo2t[i] = Wo2[o * 128 + ck];
        }
        if (i < 128) {
            float s = 0.f;
            for (int d = 0; d < 128; d++) { float v = proto[i * 128 + d]; s = fmaf(v, v, s); }
            g_psq[i] = s;
        }
    }
}

// ---------------------------------------------------------------------------
// Conv1d(k=5,same)+ReLU+maxpool2. 128 threads = 32 op x 4 quarters.
// Each thread: 2 channel pairs {2op,2op+1},{64+2op,65+2op} x 8 prepool pos.
// x tile plain float (broadcast LDS.32 + mov-dup); weights cp.async dbuf.
// ---------------------------------------------------------------------------
template <int CIN>
__global__ void __launch_bounds__(128)
conv_pool_v4(const float* __restrict__ in, const float* __restrict__ wt,
             const float* __restrict__ bias, float* __restrict__ out,
             int Lin, int Lpool) {
    constexpr int TPRE = 32;
    constexpr int XS   = TPRE + 4;   // 36
    constexpr int NCH  = CIN / 4;
    extern __shared__ char smem[];
    float* ws = (float*)smem;                      // 2 x 2560 floats
    float* xs = (float*)(smem + 2 * 2560 * 4);     // CIN*XS floats

    const int tid = threadIdx.x;
    const int op  = tid & 31;
    const int q   = tid >> 5;
    const int jb  = q * 8;
    const int b   = blockIdx.y;
    const int l0  = blockIdx.x * TPRE;

    const unsigned ws_base = (unsigned)__cvta_generic_to_shared(ws);

    for (int i = tid; i < 640; i += 128) {
        asm volatile("cp.async.ca.shared.global [%0], [%1], 16;"
                     :: "r"(ws_base + i * 16), "l"(wt + i * 4));
    }
    asm volatile("cp.async.commit_group;" ::: "memory");

    const float* inb = in + (size_t)b * Lin * CIN;
    for (int i = tid; i < XS * CIN; i += 128) {
        const int pos = i / CIN;
        const int c   = i - pos * CIN;
        const int l   = l0 - 2 + pos;
        xs[c * XS + pos] = (l >= 0 && l < Lin) ? inb[(size_t)l * CIN + c] : 0.f;
    }

    u64 accA[8], accB[8];
    {
        const float2 ba = *(const float2*)(bias + 2 * op);
        const float2 bb = *(const float2*)(bias + 64 + 2 * op);
        u64 pa, pb;
        asm("mov.b64 %0, {%1,%2};" : "=l"(pa) : "f"(ba.x), "f"(ba.y));
        asm("mov.b64 %0, {%1,%2};" : "=l"(pb) : "f"(bb.x), "f"(bb.y));
#pragma unroll
        for (int j = 0; j < 8; j++) { accA[j] = pa; accB[j] = pb; }
    }

    for (int ch = 0; ch < NCH; ch++) {
        asm volatile("cp.async.wait_group 0;" ::: "memory");
        __syncthreads();
        if (ch + 1 < NCH) {
            const float*   src = wt + (ch + 1) * 2560;
            const unsigned dst = ws_base + ((ch + 1) & 1) * 10240;
            for (int i = tid; i < 640; i += 128) {
                asm volatile("cp.async.ca.shared.global [%0], [%1], 16;"
                             :: "r"(dst + i * 16), "l"(src + i * 4));
            }
            asm volatile("cp.async.commit_group;" ::: "memory");
        }
        const float* wbuf = ws + (ch & 1) * 2560;
        const int c0 = ch * 4;
#pragma unroll
        for (int cc = 0; cc < 4; cc++) {
            const float* xc = xs + (c0 + cc) * XS + jb;
            u64 xr[12];
#pragma unroll
            for (int p = 0; p < 12; p++) xr[p] = dup2(xc[p]);  // LDS.32 bcast + mov-dup
#pragma unroll
            for (int k = 0; k < 5; k++) {
                const float* wrow = wbuf + (cc * 5 + k) * 128;
                const u64 wa = *(const u64*)(wrow + 2 * op);
                const u64 wb = *(const u64*)(wrow + 64 + 2 * op);
#pragma unroll
                for (int j = 0; j < 8; j++) {
                    ffma2(accA[j], wa, xr[j + k]);
                    ffma2(accB[j], wb, xr[j + k]);
                }
            }
        }
    }

    float* outb = out + ((size_t)b * Lpool + l0 / 2 + jb / 2) * 128;
#pragma unroll
    for (int m = 0; m < 4; m++) {
        const float2 a0 = *(const float2*)&accA[2 * m];
        const float2 a1 = *(const float2*)&accA[2 * m + 1];
        const float2 b0 = *(const float2*)&accB[2 * m];
        const float2 b1 = *(const float2*)&accB[2 * m + 1];
        float2 ra, rb;
        ra.x = fmaxf(fmaxf(a0.x, a1.x), 0.f);
        ra.y = fmaxf(fmaxf(a0.y, a1.y), 0.f);
        rb.x = fmaxf(fmaxf(b0.x, b1.x), 0.f);
        rb.y = fmaxf(fmaxf(b0.y, b1.y), 0.f);
        *(float2*)(outb + (size_t)m * 128 + 2 * op)      = ra;
        *(float2*)(outb + (size_t)m * 128 + 64 + 2 * op) = rb;
    }
}

// ---------------------------------------------------------------------------
// Fused 1x1 convs (2 layers) + ReLU + fsq. (unchanged from R4)
// ---------------------------------------------------------------------------
__global__ void __launch_bounds__(128)
fc_fused(const float* __restrict__ in, const float* __restrict__ w1t,
         const float* __restrict__ b1, const float* __restrict__ w2t,
         const float* __restrict__ b2, float* __restrict__ f,
         float* __restrict__ fsq) {
    extern __shared__ char smem[];
    float*  ws  = (float*)smem;                          // 2 x 2048 floats
    float2* hs2 = (float2*)(smem + 16384);               // [c*33 + r]
    float2* ms2 = (float2*)(smem + 16384 + 33792);

    const int tid  = threadIdx.x;
    const int op   = tid & 31;
    const int q    = tid >> 5;
    const int b    = blockIdx.y;
    const int row0 = blockIdx.x * 32;
    const unsigned ws_base = (unsigned)__cvta_generic_to_shared(ws);

    for (int i = tid; i < 512; i += 128) {
        asm volatile("cp.async.ca.shared.global [%0], [%1], 16;"
                     :: "r"(ws_base + i * 16), "l"(w1t + i * 4));
    }
    asm volatile("cp.async.commit_group;" ::: "memory");

    const float* inb = in + ((size_t)b * 256 + row0) * 128;
    for (int i = tid; i < 32 * 128; i += 128) {
        const int r = i >> 7, c = i & 127;
        const float v = inb[i];
        hs2[c * 33 + r] = make_float2(v, v);
    }

    u64 accA[8], accB[8];
    u64 pa, pb;
    {
        const float2 ba = *(const float2*)(b1 + 2 * op);
        const float2 bb = *(const float2*)(b1 + 64 + 2 * op);
        asm("mov.b64 %0, {%1,%2};" : "=l"(pa) : "f"(ba.x), "f"(ba.y));
        asm("mov.b64 %0, {%1,%2};" : "=l"(pb) : "f"(bb.x), "f"(bb.y));
#pragma unroll
        for (int j = 0; j < 8; j++) { accA[j] = pa; accB[j] = pb; }
    }

    for (int c0 = 0; c0 < 8; c0++) {
        asm volatile("cp.async.wait_group 0;" ::: "memory");
        __syncthreads();
        if (c0 + 1 < 8) {
            const float*   src = w1t + (c0 + 1) * 2048;
            const unsigned dst = ws_base + ((c0 + 1) & 1) * 8192;
            for (int i = tid; i < 512; i += 128) {
                asm volatile("cp.async.ca.shared.global [%0], [%1], 16;"
                             :: "r"(dst + i * 16), "l"(src + i * 4));
            }
            asm volatile("cp.async.commit_group;" ::: "memory");
        }
        const float* wbuf = ws + (c0 & 1) * 2048;
#pragma unroll
        for (int cc = 0; cc < 16; cc++) {
            const u64 wa = *(const u64*)(wbuf + cc * 128 + 2 * op);
            const u64 wb = *(const u64*)(wbuf + cc * 128 + 64 + 2 * op);
            const float2* xb = hs2 + (c0 * 16 + cc) * 33 + q * 8;
#pragma unroll
            for (int j = 0; j < 8; j++) {
                const u64 x = *(const u64*)(xb + j);
                ffma2(accA[j], wa, x);
                ffma2(accB[j], wb, x);
            }
        }
    }

    __syncthreads();
    for (int i = tid; i < 512; i += 128) {
        asm volatile("cp.async.ca.shared.global [%0], [%1], 16;"
                     :: "r"(ws_base + i * 16), "l"(w2t + i * 4));
    }
    asm volatile("cp.async.commit_group;" ::: "memory");

#pragma unroll
    for (int j = 0; j < 8; j++) {
        float2 a = *(const float2*)&accA[j];
        float2 c = *(const float2*)&accB[j];
        a.x = fmaxf(a.x, 0.f); a.y = fmaxf(a.y, 0.f);
        c.x = fmaxf(c.x, 0.f); c.y = fmaxf(c.y, 0.f);
        const int r = q * 8 + j;
        ms2[(2 * op)     * 33 + r] = make_float2(a.x, a.x);
        ms2[(2 * op + 1) * 33 + r] = make_float2(a.y, a.y);
        ms2[(64 + 2 * op)     * 33 + r] = make_float2(c.x, c.x);
        ms2[(64 + 2 * op + 1) * 33 + r] = make_float2(c.y, c.y);
    }

    {
        const float2 ba = *(const float2*)(b2 + 2 * op);
        const float2 bb = *(const float2*)(b2 + 64 + 2 * op);
        asm("mov.b64 %0, {%1,%2};" : "=l"(pa) : "f"(ba.x), "f"(ba.y));
        asm("mov.b64 %0, {%1,%2};" : "=l"(pb) : "f"(bb.x), "f"(bb.y));
#pragma unroll
        for (int j = 0; j < 8; j++) { accA[j] = pa; accB[j] = pb; }
    }

    for (int c0 = 0; c0 < 8; c0++) {
        asm volatile("cp.async.wait_group 0;" ::: "memory");
        __syncthreads();
        if (c0 + 1 < 8) {
            const float*   src = w2t + (c0 + 1) * 2048;
            const unsigned dst = ws_base + ((c0 + 1) & 1) * 8192;
            for (int i = tid; i < 512; i += 128) {
                asm volatile("cp.async.ca.shared.global [%0], [%1], 16;"
                             :: "r"(dst + i * 16), "l"(src + i * 4));
            }
            asm volatile("cp.async.commit_group;" ::: "memory");
        }
        const float* wbuf = ws + (c0 & 1) * 2048;
#pragma unroll
        for (int cc = 0; cc < 16; cc++) {
            const u64 wa = *(const u64*)(wbuf + cc * 128 + 2 * op);
            const u64 wb = *(const u64*)(wbuf + cc * 128 + 64 + 2 * op);
            const float2* xb = ms2 + (c0 * 16 + cc) * 33 + q * 8;
#pragma unroll
            for (int j = 0; j < 8; j++) {
                const u64 x = *(const u64*)(xb + j);
                ffma2(accA[j], wa, x);
                ffma2(accB[j], wb, x);
            }
        }
    }

    float* fb = f + ((size_t)b * 256 + row0 + q * 8) * 128;
#pragma unroll
    for (int j = 0; j < 8; j++) {
        float2 a = *(const float2*)&accA[j];
        float2 c = *(const float2*)&accB[j];
        a.x = fmaxf(a.x, 0.f); a.y = fmaxf(a.y, 0.f);
        c.x = fmaxf(c.x, 0.f); c.y = fmaxf(c.y, 0.f);
        *(float2*)(fb + (size_t)j * 128 + 2 * op)      = a;
        *(float2*)(fb + (size_t)j * 128 + 64 + 2 * op) = c;
        float s = a.x * a.x + a.y * a.y + c.x * c.x + c.y * c.y;
#pragma unroll
        for (int off = 16; off; off >>= 1) s += __shfl_down_sync(0xffffffffu, s, off);
        if (op == 0) fsq[(size_t)b * 256 + row0 + q * 8 + j] = s;
    }
}

// ---------------------------------------------------------------------------
// Prototype L2 distances + partial min over 64 rows per block. (unchanged)
// ---------------------------------------------------------------------------
__global__ void __launch_bounds__(128)
dist_v2(const float* __restrict__ proto) {
    extern __shared__ char smem[];
    float* protoS = (float*)smem;                 // [p*130 + d]
    float* fs     = (float*)(smem + 66560);       // [r*128 + d]

    const int b = blockIdx.y, chunk = blockIdx.x;
    const int p = threadIdx.x;

    for (int i = p; i < 128 * 128; i += 128) {
        const int pp = i >> 7, d = i & 127;
        protoS[pp * 130 + d] = proto[i];
    }
    const float psqv = g_psq[p];
    const float* fb = g_f   + ((size_t)(b * 256 + chunk * 64)) * 128;
    const float* fq = g_fsq + b * 256 + chunk * 64;
    float best = 3.4e38f;

    for (int l0 = 0; l0 < 64; l0 += 8) {
        __syncthreads();
        for (int i = p; i < 1024; i += 128) fs[i] = fb[(size_t)l0 * 128 + i];
        __syncthreads();

        u64 acc2[8];
#pragma unroll
        for (int r = 0; r < 8; r++) acc2[r] = 0ull;
#pragma unroll
        for (int dc = 0; dc < 4; dc++) {
            u64 ptr_[16];
#pragma unroll
            for (int i = 0; i < 16; i++)
                ptr_[i] = *(const u64*)(protoS + p * 130 + dc * 32 + 2 * i);
#pragma unroll
            for (int r = 0; r < 8; r++) {
                const float* fr = fs + r * 128 + dc * 32;
#pragma unroll
                for (int i = 0; i < 16; i++)
                    ffma2(acc2[r], ptr_[i], *(const u64*)(fr + 2 * i));
            }
        }
#pragma unroll
        for (int r = 0; r < 8; r++) {
            const float2 a = *(const float2*)&acc2[r];
            const float dot = a.x + a.y;
            const float d2 = fq[l0 + r] - 2.f * dot + psqv;
            best = fminf(best, d2);
        }
    }
    g_minpart[(b * 4 + chunk) * 128 + p] = best;
}

// ---------------------------------------------------------------------------
// Final head.  d_out[0:64] = out(32,2); d_out[64:4160] = min_dis(32,128).
// ---------------------------------------------------------------------------
__global__ void final_kernel(const int* __restrict__ classes, float* __restrict__ outp) {
    const int b = blockIdx.x, p = threadIdx.x;
    float m = g_minpart[(b * 4 + 0) * 128 + p];
    m = fminf(m, g_minpart[(b * 4 + 1) * 128 + p]);
    m = fminf(m, g_minpart[(b * 4 + 2) * 128 + p]);
    m = fminf(m, g_minpart[(b * 4 + 3) * 128 + p]);
    const float dis = sqrtf(fmaxf(m, 1e-12f));
    const float sim = logf((dis + 1.f) / (dis + 1e-4f));
    outp[64 + b * 128 + p] = dis;

    __shared__ float ss[128];
    ss[p] = sim;
    __syncthreads();
    if (p < 2) {
        float s = 0.f;
        for (int q = 0; q < 128; q++)
            s += ss[q] * ((classes[q] == p) ? 1.f : -0.5f);
        outp[b * 2 + p] = 1.f / (1.f + expf(-s));
    }
}

// ---------------------------------------------------------------------------
extern "C" void kernel_launch(void* const* d_in, const int* in_sizes, int n_in,
                              void* d_out, int out_size) {
    const float* x     = (const float*)d_in[0];
    const float* W1    = (const float*)d_in[1];
    const float* b1    = (const float*)d_in[2];
    const float* W2    = (const float*)d_in[3];
    const float* b2    = (const float*)d_in[4];
    const float* W3    = (const float*)d_in[5];
    const float* b3    = (const float*)d_in[6];
    const float* Wo1   = (const float*)d_in[7];
    const float* bo1   = (const float*)d_in[8];
    const float* Wo2   = (const float*)d_in[9];
    const float* bo2   = (const float*)d_in[10];
    const float* proto = (const float*)d_in[11];
    const int*   cls   = (const int*)d_in[12];
    float* out = (float*)d_out;
    (void)in_sizes; (void)n_in; (void)out_size;

    void *h1, *h2, *h3, *f, *fsq, *w1t, *w2t, *w3t, *wo1t, *wo2t;
    cudaGetSymbolAddress(&h1, g_h1);
    cudaGetSymbolAddress(&h2, g_h2);
    cudaGetSymbolAddress(&h3, g_h3);
    cudaGetSymbolAddress(&f,  g_f);
    cudaGetSymbolAddress(&fsq, g_fsq);
    cudaGetSymbolAddress(&w1t, g_w1t);
    cudaGetSymbolAddress(&w2t, g_w2t);
    cudaGetSymbolAddress(&w3t, g_w3t);
    cudaGetSymbolAddress(&wo1t, g_wo1t);
    cudaGetSymbolAddress(&wo2t, g_wo2t);

    const int smem76  = 2 * 2560 * 4 + 76  * 36 * 4;   // 31424
    const int smem128 = 2 * 2560 * 4 + 128 * 36 * 4;   // 38912
    const int smemfc  = 16384 + 2 * 33792;             // 83968
    const int smemd   = 66560 + 4096;                  // 70656
    cudaFuncSetAttribute(conv_pool_v4<76>,  cudaFuncAttributeMaxDynamicSharedMemorySize, smem76);
    cudaFuncSetAttribute(conv_pool_v4<128>, cudaFuncAttributeMaxDynamicSharedMemorySize, smem128);
    cudaFuncSetAttribute(fc_fused, cudaFuncAttributeMaxDynamicSharedMemorySize, smemfc);
    cudaFuncSetAttribute(dist_v2,  cudaFuncAttributeMaxDynamicSharedMemorySize, smemd);

    prep_kernel<<<256, 256>>>(W1, W2, W3, Wo1, Wo2, proto);

    conv_pool_v4<76> <<<dim3(64, NB), 128, smem76 >>>(x,          (const float*)w1t, b1, (float*)h1, 2048, 1024);
    conv_pool_v4<128><<<dim3(32, NB), 128, smem128>>>((float*)h1, (const float*)w2t, b2, (float*)h2, 1024, 512);
    conv_pool_v4<128><<<dim3(16, NB), 128, smem128>>>((float*)h2, (const float*)w3t, b3, (float*)h3, 512,  256);

    fc_fused<<<dim3(8, NB), 128, smemfc>>>((const float*)h3, (const float*)wo1t, bo1,
                                           (const float*)wo2t, bo2, (float*)f, (float*)fsq);
    dist_v2<<<dim3(4, NB), 128, smemd>>>(proto);
    final_kernel<<<NB, 128>>>(cls, out);
}